// round 7
// baseline (speedup 1.0000x reference)
#include <cuda_runtime.h>
#include <cstdint>

#define DIMC 384
#define CPC  192                 // channels per CTA (cluster of 2 covers 384)
#define NP   49
#define HW   112
#define CH_STRIDE (112 * 112)
#define NT   224                 // 7 warps; 192*49/224 = 42 elems/thread exactly

__global__ void __launch_bounds__(NT, 5) __cluster_dims__(2, 1, 1)
attn_ds_kernel(
    const float* __restrict__ hr,   // (8, 384, 112, 112)
    const float* __restrict__ du,   // (8, 16, 16, 1)
    const float* __restrict__ aw,   // (384,)
    const float* __restrict__ ab,   // (1,)
    const float* __restrict__ wt,   // (7,7) -> 49
    const float* __restrict__ bt,   // (7,7) -> 49
    float* __restrict__ out)        // (8, 384, 16, 16)
{
    extern __shared__ float patch[];          // [192][49], pitch 49 floats
    __shared__ float s_aw[CPC];
    __shared__ float s_part[NP];              // own partial logits (192 ch)
    __shared__ float s_peer[NP];              // peer's partials (written remotely)
    __shared__ float s_attn[NP];

    const int tid  = threadIdx.x;             // 0..223
    const int lane = tid & 31;
    const int wid  = tid >> 5;                // 0..6
    const int rank = blockIdx.x & 1;          // cluster rank (cluster dims (2,1,1))
    const int pix  = blockIdx.x >> 1;         // b*256 + h*16 + w
    const int b    = pix >> 8;
    const int h    = (pix >> 4) & 15;
    const int wcol = pix & 15;
    const int c0   = rank * CPC;

    // Patch origin (stride==K: exact tiling), this CTA's channel half.
    const float* src = hr + ((size_t)b * DIMC + c0) * CH_STRIDE + (h * 7) * HW + (wcol * 7);

    if (tid < CPC) s_aw[tid] = aw[c0 + tid];

    // ---- Phase 1: load 49x192 patch half into SMEM, layout [c*49 + p] ----
    // Linear idx -> STS write-linear; magic-multiply address math:
    //   c = idx/49 == (idx*42800)>>21 (exact idx<43690); py = p/7 == (p*9363)>>16
    //   py*HW + px == p + 105*py.   6 batches of 7 LDGs keep MLP >= 7/warp.
    #pragma unroll
    for (int itb = 0; itb < 6; ++itb) {
        float v[7];
        #pragma unroll
        for (int j = 0; j < 7; ++j) {
            unsigned idx = (unsigned)tid + (unsigned)(itb * 7 + j) * NT;
            unsigned c   = (idx * 42800u) >> 21;
            unsigned p   = idx - c * 49u;
            unsigned py  = (p * 9363u) >> 16;
            v[j] = src[(size_t)c * CH_STRIDE + p + 105u * py];
        }
        #pragma unroll
        for (int j = 0; j < 7; ++j)
            patch[tid + (itb * 7 + j) * NT] = v[j];
    }
    __syncthreads();

    // ---- Phase 2: partial logits over this CTA's 192 channels ----
    // 7 warps x exactly 7 p-values. Banks (17c+p)%32 bijective -> conflict-free.
    #pragma unroll
    for (int p = wid; p < NP; p += 7) {
        float acc0 = 0.0f, acc1 = 0.0f;
        #pragma unroll
        for (int k = 0; k < 6; k += 2) {
            int cA = lane + k * 32;
            int cB = lane + (k + 1) * 32;
            acc0 = fmaf(patch[cA * NP + p], s_aw[cA], acc0);
            acc1 = fmaf(patch[cB * NP + p], s_aw[cB], acc1);
        }
        float acc = acc0 + acc1;
        #pragma unroll
        for (int o = 16; o > 0; o >>= 1)
            acc += __shfl_xor_sync(0xffffffffu, acc, o);
        if (lane == 0) s_part[p] = acc;
    }
    __syncthreads();

    // ---- Push own partials into peer's s_peer (DSMEM store, fire-and-forget) ----
    if (tid < NP) {
        uint32_t dst = (uint32_t)__cvta_generic_to_shared(&s_peer[tid]);
        uint32_t rem;
        asm ("mapa.shared::cluster.u32 %0, %1, %2;" : "=r"(rem) : "r"(dst), "r"(rank ^ 1));
        float v = s_part[tid];
        asm volatile("st.shared::cluster.f32 [%0], %1;" :: "r"(rem), "f"(v) : "memory");
    }
    // Cluster barrier: release makes our remote stores visible; acquire makes
    // the peer's stores into our s_peer visible. No cross-CTA access after this.
    asm volatile("barrier.cluster.arrive.aligned;" ::: "memory");
    asm volatile("barrier.cluster.wait.aligned;"   ::: "memory");

    // ---- Phase 3: combine + masked affine + softmax over 49 (warp 0) ----
    if (wid == 0) {
        const float m  = (du[pix] > 0.2f) ? 1.0f : 0.0f;   // scalar mask per pixel
        const float a0 = ab[0];
        const int p1 = lane + 32;
        float l0 = (s_part[lane] + s_peer[lane] + a0) * m * wt[lane] + bt[lane];
        float l1 = (p1 < NP)
                 ? (s_part[p1] + s_peer[p1] + a0) * m * wt[p1] + bt[p1]
                 : -1e30f;
        float mx = fmaxf(l0, l1);
        #pragma unroll
        for (int o = 16; o > 0; o >>= 1)
            mx = fmaxf(mx, __shfl_xor_sync(0xffffffffu, mx, o));
        float e0 = __expf(l0 - mx);
        float e1 = (p1 < NP) ? __expf(l1 - mx) : 0.0f;
        float s = e0 + e1;
        #pragma unroll
        for (int o = 16; o > 0; o >>= 1)
            s += __shfl_xor_sync(0xffffffffu, s, o);
        const float inv = 1.0f / s;
        s_attn[lane] = e0 * inv;
        if (p1 < NP) s_attn[p1] = e1 * inv;
    }
    __syncthreads();

    // ---- Phase 4: out[c] = sum_p patch[c][p] * attn[p] (own 192 channels) ----
    if (tid < CPC) {
        float a0 = 0.0f, a1 = 0.0f;
        #pragma unroll
        for (int p = 0; p < 48; p += 2) {
            a0 = fmaf(patch[tid * NP + p],     s_attn[p],     a0);
            a1 = fmaf(patch[tid * NP + p + 1], s_attn[p + 1], a1);
        }
        a0 = fmaf(patch[tid * NP + 48], s_attn[48], a0);
        __stcg(&out[((size_t)b * DIMC + c0 + tid) * 256 + h * 16 + wcol], a0 + a1);
    }
}

extern "C" void kernel_launch(void* const* d_in, const int* in_sizes, int n_in,
                              void* d_out, int out_size)
{
    const float* hr = (const float*)d_in[0];  // hr_feats
    // d_in[1] = guidance (unused, zeros)
    const float* du = (const float*)d_in[2];  // dropout_u
    const float* aw = (const float*)d_in[3];
    const float* ab = (const float*)d_in[4];
    const float* wt = (const float*)d_in[5];
    const float* bt = (const float*)d_in[6];
    float* out = (float*)d_out;

    const size_t smem = (size_t)CPC * NP * sizeof(float);  // 37632 B dynamic
    cudaFuncSetAttribute(attn_ds_kernel,
                         cudaFuncAttributeMaxDynamicSharedMemorySize, (int)smem);
    // 2048 pixels x 2 CTAs/cluster; compile-time cluster dims (2,1,1).
    attn_ds_kernel<<<4096, NT, smem>>>(hr, du, aw, ab, wt, bt, out);
}